// round 10
// baseline (speedup 1.0000x reference)
#include <cuda_runtime.h>

#define Bsz 64
#define Tn  16384
#define H1n 64
#define H2n 8
#define RING 64
#define RSTR 9   // ring row stride -> conflict-free LDS across lanes

typedef unsigned long long u64;

__device__ __forceinline__ u64 pk2(float lo, float hi) {
    u64 r; asm("mov.b64 %0, {%1,%2};" : "=l"(r) : "f"(lo), "f"(hi)); return r;
}
__device__ __forceinline__ float2 upk2(u64 v) {
    float2 f; asm("mov.b64 {%0,%1}, %2;" : "=f"(f.x), "=f"(f.y) : "l"(v)); return f;
}
__device__ __forceinline__ void fma2(u64 &d, u64 a, u64 b) {
    asm("fma.rn.f32x2 %0, %1, %2, %0;" : "+l"(d) : "l"(a), "l"(b));
}
__device__ __forceinline__ void add2(u64 &d, u64 a) {
    asm("add.rn.f32x2 %0, %0, %1;" : "+l"(d) : "l"(a));
}
__device__ __forceinline__ float tanh_(float v) {
    float r; asm("tanh.approx.f32 %0, %1;" : "=f"(r) : "f"(v)); return r;
}
__device__ __forceinline__ float sigm(float v) {
    return fmaf(0.5f, tanh_(0.5f * v), 0.5f);
}

// One block per PAIR of batch rows (weights shared across batch!). 12 warps:
//   warps 0-7 : layer-1, lane = cellLocal*4 + gate, 8 cells/warp. Each lane
//               runs TWO 64-dots (batch0/batch1) off the SAME weight regs:
//               ILP x2, weight regs amortized.
//   warp 8    : layer-2 update (lags 2). Lanes 0-7 = batch0 cells,
//               lanes 8-15 = batch1 cells. Gates in-lane, partials via
//               float4 LDS, h2 via smem double buffer.
//   warp 9    : layer-2 input dot Wih2@h1[t-1] for batch0 (full 64-dot).
//   warp 10   : same for batch1.
//   warp 11   : batched output projection for both batches.
// h1 in per-batch depth-4 smem rings; one __syncthreads per step.
__global__ void __launch_bounds__(384, 1) lstm2_kernel(
    const float* __restrict__ x,
    const float* __restrict__ Wih1,
    const float* __restrict__ Whh1,
    const float* __restrict__ b1,
    const float* __restrict__ Wih2,
    const float* __restrict__ Whh2,
    const float* __restrict__ b2,
    const float* __restrict__ Wout,
    const float* __restrict__ bout,
    float* __restrict__ out)
{
    const int bp   = blockIdx.x;          // batch pair index
    const int b0   = 2 * bp;
    const int tid  = threadIdx.x;
    const int wid  = tid >> 5;
    const int lane = tid & 31;

    __shared__ __align__(16) float h1ring[2][4][H1n];   // [batch][phase][cell]
    __shared__ __align__(16) float pbuf[2][2][32];      // [phase][batch][cell*4+gate]
    __shared__ __align__(16) float h2s[2][2][H2n];      // [phase][batch][cell]
    __shared__ float h2ring[2][RING * RSTR];

    const float* xb0 = x + (size_t)b0 * Tn;
    const float* xb1 = xb0 + Tn;
    float*       yb0 = out + (size_t)b0 * Tn;
    float*       yb1 = yb0 + Tn;

    u64   w[32];
    float wih = 0.f, bias = 0.f;
    float c1A = 0.f, h1vA = 0.f, c1B = 0.f, h1vB = 0.f;
    float w2h[8];
    float bias2 = 0.f, boutv = 0.f;
    float c2 = 0.f, h2v = 0.f;
    int   cell = 0, q = 0;

    if (wid < 8) {
        cell = wid * 8 + (lane >> 2);
        q    = lane & 3;
        const int row = q * H1n + cell;
        const float2* wp = (const float2*)(Whh1 + row * H1n);
        #pragma unroll
        for (int k = 0; k < 32; k++) { float2 f = wp[k]; w[k] = pk2(f.x, f.y); }
        wih  = Wih1[row];
        bias = b1[row];
        if (tid < H1n) { h1ring[0][3][tid] = 0.0f; h1ring[1][3][tid] = 0.0f; }
    } else if (wid == 8) {
        // lanes 0-15: bt = lane>>3, cell = lane&7, all 4 gates in-lane
        if (lane < 16) {
            const int cw = lane & 7;
            #pragma unroll
            for (int g = 0; g < 4; g++) {
                const int row = g * H2n + cw;
                const float2* wp = (const float2*)(Whh2 + row * H2n);
                #pragma unroll
                for (int j = 0; j < 4; j++) { float2 f = wp[j]; w[4 * g + j] = pk2(f.x, f.y); }
            }
            h2s[0][lane >> 3][cw] = 0.0f;
            h2s[1][lane >> 3][cw] = 0.0f;
        }
    } else if (wid <= 10) { // warps 9,10 : full input dot for one batch
        cell = lane >> 2;
        q    = lane & 3;
        const int row = q * H2n + cell;
        const float2* wp = (const float2*)(Wih2 + row * H1n);
        #pragma unroll
        for (int k = 0; k < 32; k++) { float2 f = wp[k]; w[k] = pk2(f.x, f.y); }
        bias2 = b2[row];
    } else { // wid == 11 : output projection for both batches
        #pragma unroll
        for (int k = 0; k < 8; k++) w2h[k] = Wout[k];
        boutv = bout[0];
    }
    __syncthreads();

    float xA_cur = xb0[0], xA_n1 = xb0[1];
    float xB_cur = xb1[0], xB_n1 = xb1[1];

    #pragma unroll 2
    for (int t = 0; t <= Tn + 1; ++t) {
        if (wid < 8) {
            if (t < Tn) {
                float xA_n2 = (t + 2 < Tn) ? xb0[t + 2] : 0.0f;
                float xB_n2 = (t + 2 < Tn) ? xb1[t + 2] : 0.0f;
                u64 z  = pk2(0.f, 0.f);
                u64 a0 = pk2(fmaf(xA_cur, wih, bias), 0.0f), a1 = z;
                u64 b0r = pk2(fmaf(xB_cur, wih, bias), 0.0f), b1r = z;
                const int rph = (t + 3) & 3;
                const ulonglong2* hp0 = (const ulonglong2*)(&h1ring[0][rph][0]);
                const ulonglong2* hp1 = (const ulonglong2*)(&h1ring[1][rph][0]);
                #pragma unroll
                for (int k = 0; k < 8; k++) {
                    ulonglong2 ha0 = hp0[2 * k];
                    ulonglong2 hb0 = hp0[2 * k + 1];
                    ulonglong2 ha1 = hp1[2 * k];
                    ulonglong2 hb1 = hp1[2 * k + 1];
                    fma2(a0,  w[4 * k + 0], ha0.x);
                    fma2(b0r, w[4 * k + 0], ha1.x);
                    fma2(a1,  w[4 * k + 1], ha0.y);
                    fma2(b1r, w[4 * k + 1], ha1.y);
                    fma2(a0,  w[4 * k + 2], hb0.x);
                    fma2(b0r, w[4 * k + 2], hb1.x);
                    fma2(a1,  w[4 * k + 3], hb0.y);
                    fma2(b1r, w[4 * k + 3], hb1.y);
                }
                add2(a0, a1); add2(b0r, b1r);
                float2 sa = upk2(a0);
                float2 sb = upk2(b0r);
                float gA = sa.x + sa.y;
                float gB = sb.x + sb.y;
                float actA = (q == 2) ? tanh_(gA) : sigm(gA);
                float actB = (q == 2) ? tanh_(gB) : sigm(gB);
                const unsigned bl = lane & ~3u;
                float aiA = __shfl_sync(0xffffffffu, actA, bl + 0);
                float afA = __shfl_sync(0xffffffffu, actA, bl + 1);
                float agA = __shfl_sync(0xffffffffu, actA, bl + 2);
                float aoA = __shfl_sync(0xffffffffu, actA, bl + 3);
                float aiB = __shfl_sync(0xffffffffu, actB, bl + 0);
                float afB = __shfl_sync(0xffffffffu, actB, bl + 1);
                float agB = __shfl_sync(0xffffffffu, actB, bl + 2);
                float aoB = __shfl_sync(0xffffffffu, actB, bl + 3);
                c1A  = fmaf(afA, c1A, aiA * agA);
                c1B  = fmaf(afB, c1B, aiB * agB);
                h1vA = aoA * tanh_(c1A);
                h1vB = aoB * tanh_(c1B);
                if (q == 0) {
                    h1ring[0][t & 3][cell] = h1vA;
                    h1ring[1][t & 3][cell] = h1vB;
                }
                xA_cur = xA_n1; xA_n1 = xA_n2;
                xB_cur = xB_n1; xB_n1 = xB_n2;
            }
        } else if (wid == 8) {
            if (t >= 2 && lane < 16) {
                const int s  = t - 2;
                const int ph = (t - 1) & 1;
                const int bt = lane >> 3;
                const int cw = lane & 7;
                const float4 p0 = *(const float4*)&pbuf[ph][bt][cw * 4];
                float gi = p0.x, gf = p0.y, gg = p0.z, go = p0.w;
                const u64* hq = (const u64*)&h2s[ph][bt][0];
                u64 h01 = hq[0], h23 = hq[1], h45 = hq[2], h67 = hq[3];
                u64 A = pk2(gi, 0.f), B = pk2(gf, 0.f);
                u64 C = pk2(gg, 0.f), D = pk2(go, 0.f);
                fma2(A, w[0],  h01); fma2(B, w[4],  h01);
                fma2(C, w[8],  h01); fma2(D, w[12], h01);
                fma2(A, w[1],  h23); fma2(B, w[5],  h23);
                fma2(C, w[9],  h23); fma2(D, w[13], h23);
                fma2(A, w[2],  h45); fma2(B, w[6],  h45);
                fma2(C, w[10], h45); fma2(D, w[14], h45);
                fma2(A, w[3],  h67); fma2(B, w[7],  h67);
                fma2(C, w[11], h67); fma2(D, w[15], h67);
                float2 fa = upk2(A), fb = upk2(B), fc = upk2(C), fd = upk2(D);
                float ti = sigm(fa.x + fa.y);
                float tf = sigm(fb.x + fb.y);
                float tg = tanh_(fc.x + fc.y);
                float to = sigm(fd.x + fd.y);
                c2  = fmaf(tf, c2, ti * tg);
                h2v = to * tanh_(c2);
                h2s[t & 1][bt][cw] = h2v;
                h2ring[bt][(s & (RING - 1)) * RSTR + cw] = h2v;
            }
        } else if (wid <= 10) { // warps 9,10 : input dot for batch (wid-9)
            if (t >= 1 && t <= Tn) {
                const int s  = t - 1;
                const int bt = wid - 9;
                u64 a0 = pk2(bias2, 0.0f), a1 = pk2(0.f, 0.f);
                const ulonglong2* hp = (const ulonglong2*)(&h1ring[bt][s & 3][0]);
                #pragma unroll
                for (int k = 0; k < 8; k++) {
                    ulonglong2 ha = hp[2 * k];
                    ulonglong2 hb = hp[2 * k + 1];
                    fma2(a0, w[4 * k + 0], ha.x);
                    fma2(a1, w[4 * k + 1], ha.y);
                    fma2(a0, w[4 * k + 2], hb.x);
                    fma2(a1, w[4 * k + 3], hb.y);
                }
                add2(a0, a1);
                float2 s2 = upk2(a0);
                pbuf[t & 1][bt][lane] = s2.x + s2.y;
            }
        } else { // wid == 11 : batched output projection, both batches
            if ((t & 31) == 0 && t >= 32) {
                const int s2i = t - 34 + lane;   // window [t-34, t-3]
                if (s2i >= 0) {
                    const int rs = (s2i & (RING - 1)) * RSTR;
                    const float* r0 = &h2ring[0][rs];
                    const float* r1 = &h2ring[1][rs];
                    float acc0 = boutv, acc1 = 0.f;
                    float acd0 = boutv, acd1 = 0.f;
                    #pragma unroll
                    for (int k = 0; k < 4; k++) {
                        acc0 = fmaf(r0[2 * k],     w2h[2 * k],     acc0);
                        acc1 = fmaf(r0[2 * k + 1], w2h[2 * k + 1], acc1);
                        acd0 = fmaf(r1[2 * k],     w2h[2 * k],     acd0);
                        acd1 = fmaf(r1[2 * k + 1], w2h[2 * k + 1], acd1);
                    }
                    yb0[s2i] = acc0 + acc1 + xb0[s2i];
                    yb1[s2i] = acd0 + acd1 + xb1[s2i];
                }
            }
        }
        __syncthreads();
    }

    // tail: y for the last two steps for both batches
    if (wid == 11 && lane < 2) {
        const int s2i = Tn - 2 + lane;
        const int rs = (s2i & (RING - 1)) * RSTR;
        #pragma unroll
        for (int bt = 0; bt < 2; bt++) {
            const float* r = &h2ring[bt][rs];
            float acc0 = boutv, acc1 = 0.f;
            #pragma unroll
            for (int k = 0; k < 4; k++) {
                acc0 = fmaf(r[2 * k],     w2h[2 * k],     acc0);
                acc1 = fmaf(r[2 * k + 1], w2h[2 * k + 1], acc1);
            }
            if (bt == 0) yb0[s2i] = acc0 + acc1 + xb0[s2i];
            else         yb1[s2i] = acc0 + acc1 + xb1[s2i];
        }
    }

    // final states: layout  y | h1 | c1 | h2 | c2  (each with leading dim 1)
    const int OH1 = Bsz * Tn;
    const int OC1 = OH1 + Bsz * H1n;
    const int OH2 = OC1 + Bsz * H1n;
    const int OC2 = OH2 + Bsz * H2n;
    if (wid < 8) {
        if (q == 0) {
            out[OH1 + b0 * H1n + cell]        = h1vA;
            out[OC1 + b0 * H1n + cell]        = c1A;
            out[OH1 + (b0 + 1) * H1n + cell]  = h1vB;
            out[OC1 + (b0 + 1) * H1n + cell]  = c1B;
        }
    } else if (wid == 8) {
        if (lane < 16) {
            const int bt = lane >> 3;
            const int cw = lane & 7;
            out[OH2 + (b0 + bt) * H2n + cw] = h2v;
            out[OC2 + (b0 + bt) * H2n + cw] = c2;
        }
    }
}

extern "C" void kernel_launch(void* const* d_in, const int* in_sizes, int n_in,
                              void* d_out, int out_size) {
    const float* x     = (const float*)d_in[0];
    const float* Wih1  = (const float*)d_in[1];
    const float* Whh1  = (const float*)d_in[2];
    const float* b1    = (const float*)d_in[3];
    const float* Wih2  = (const float*)d_in[4];
    const float* Whh2  = (const float*)d_in[5];
    const float* b2    = (const float*)d_in[6];
    const float* Wout  = (const float*)d_in[7];
    const float* bout  = (const float*)d_in[8];
    float* out = (float*)d_out;

    lstm2_kernel<<<Bsz / 2, 384>>>(x, Wih1, Whh1, b1, Wih2, Whh2, b2, Wout, bout, out);
}

// round 11
// speedup vs baseline: 1.4930x; 1.4930x over previous
#include <cuda_runtime.h>

#define Bsz 64
#define Tn  16384
#define H1n 64
#define H2n 8
#define RING 64
#define RSTR 9   // ring row stride -> conflict-free LDS across lanes

typedef unsigned long long u64;

__device__ __forceinline__ u64 pk2(float lo, float hi) {
    u64 r; asm("mov.b64 %0, {%1,%2};" : "=l"(r) : "f"(lo), "f"(hi)); return r;
}
__device__ __forceinline__ float2 upk2(u64 v) {
    float2 f; asm("mov.b64 {%0,%1}, %2;" : "=f"(f.x), "=f"(f.y) : "l"(v)); return f;
}
__device__ __forceinline__ void fma2(u64 &d, u64 a, u64 b) {
    asm("fma.rn.f32x2 %0, %1, %2, %0;" : "+l"(d) : "l"(a), "l"(b));
}
__device__ __forceinline__ void add2(u64 &d, u64 a) {
    asm("add.rn.f32x2 %0, %0, %1;" : "+l"(d) : "l"(a));
}
__device__ __forceinline__ float tanh_(float v) {
    float r; asm("tanh.approx.f32 %0, %1;" : "=f"(r) : "f"(v)); return r;
}
__device__ __forceinline__ float sigm(float v) {
    return fmaf(0.5f, tanh_(0.5f * v), 0.5f);
}

// Topology = R7 (best): one block per batch row, 12 warps.
//   warps 0-7 : layer-1, lane = cellLocal*4 + gate, 8 cells/warp, 64-dot.
//   warp 8    : layer-2 update (lags 2), one lane per cell (lanes 0-7).
//   warps 9-11: layer-2 input dot K-split 24/24/16, one step ahead.
//               warp 11 also does batched output projection.
// NEW: main loop manually unrolled x4 with COMPILE-TIME ring slots/phases
// and float4 x loads (1 LDG.128 per 4 steps); guarded generic step only in
// prologue/epilogue.

#define L1_STEP(T, XC, RSLOT, WSLOT) do {                                   \
    u64 a0 = pk2(fmaf((XC), wih, bias), 0.0f);                              \
    u64 a1 = pk2(0.f, 0.f), a2 = a1, a3 = a1;                               \
    const ulonglong2* hp = (const ulonglong2*)(&h1ring[(RSLOT)][0]);        \
    _Pragma("unroll")                                                       \
    for (int k = 0; k < 8; k++) {                                           \
        ulonglong2 ha = hp[2 * k];                                          \
        ulonglong2 hb = hp[2 * k + 1];                                      \
        fma2(a0, w[4 * k + 0], ha.x);                                       \
        fma2(a1, w[4 * k + 1], ha.y);                                       \
        fma2(a2, w[4 * k + 2], hb.x);                                       \
        fma2(a3, w[4 * k + 3], hb.y);                                       \
    }                                                                       \
    add2(a0, a1); add2(a2, a3); add2(a0, a2);                               \
    float2 s2 = upk2(a0);                                                   \
    float g = s2.x + s2.y;                                                  \
    float act = (q == 2) ? tanh_(g) : sigm(g);                              \
    float ai = __shfl_sync(0xffffffffu, act, bl + 0);                       \
    float af = __shfl_sync(0xffffffffu, act, bl + 1);                       \
    float ag = __shfl_sync(0xffffffffu, act, bl + 2);                       \
    float ao = __shfl_sync(0xffffffffu, act, bl + 3);                       \
    c1  = fmaf(af, c1, ai * ag);                                            \
    h1v = ao * tanh_(c1);                                                   \
    if (q == 0) h1ring[(WSLOT)][cell] = h1v;                                \
} while (0)

#define W8_STEP(T, PH, WPH) do {                                            \
    if (lane < H2n) {                                                       \
        const float4 p0 = *(const float4*)&pbuf[(PH)][0][lane * 4];         \
        const float4 p1 = *(const float4*)&pbuf[(PH)][1][lane * 4];         \
        const float4 p2 = *(const float4*)&pbuf[(PH)][2][lane * 4];         \
        float gi = (p0.x + p1.x) + p2.x;                                    \
        float gf = (p0.y + p1.y) + p2.y;                                    \
        float gg = (p0.z + p1.z) + p2.z;                                    \
        float go = (p0.w + p1.w) + p2.w;                                    \
        const u64* hq = (const u64*)&h2s[(PH)][0];                          \
        u64 h01 = hq[0], h23 = hq[1], h45 = hq[2], h67 = hq[3];             \
        u64 A = pk2(gi, 0.f), B = pk2(gf, 0.f);                             \
        u64 C = pk2(gg, 0.f), D = pk2(go, 0.f);                             \
        fma2(A, w[0],  h01); fma2(B, w[4],  h01);                           \
        fma2(C, w[8],  h01); fma2(D, w[12], h01);                           \
        fma2(A, w[1],  h23); fma2(B, w[5],  h23);                           \
        fma2(C, w[9],  h23); fma2(D, w[13], h23);                           \
        fma2(A, w[2],  h45); fma2(B, w[6],  h45);                           \
        fma2(C, w[10], h45); fma2(D, w[14], h45);                           \
        fma2(A, w[3],  h67); fma2(B, w[7],  h67);                           \
        fma2(C, w[11], h67); fma2(D, w[15], h67);                           \
        float2 fa = upk2(A), fb = upk2(B), fc = upk2(C), fd = upk2(D);      \
        float ti = sigm(fa.x + fa.y);                                       \
        float tf = sigm(fb.x + fb.y);                                       \
        float tg = tanh_(fc.x + fc.y);                                      \
        float to = sigm(fd.x + fd.y);                                       \
        c2  = fmaf(tf, c2, ti * tg);                                        \
        h2v = to * tanh_(c2);                                               \
        h2s[(WPH)][lane] = h2v;                                             \
        h2ring[(((T) - 2) & (RING - 1)) * RSTR + lane] = h2v;               \
    }                                                                       \
} while (0)

#define HELPER_STEP(T, RSLOT, WPH) do {                                     \
    u64 a0 = pk2(bias2, 0.0f), a1 = pk2(0.f, 0.f);                          \
    if (wid == 9) {                                                         \
        const ulonglong2* hp = (const ulonglong2*)(&h1ring[(RSLOT)][0]);    \
        _Pragma("unroll")                                                   \
        for (int k = 0; k < 3; k++) {                                       \
            ulonglong2 ha = hp[2 * k]; ulonglong2 hb = hp[2 * k + 1];       \
            fma2(a0, w[4 * k + 0], ha.x); fma2(a1, w[4 * k + 1], ha.y);     \
            fma2(a0, w[4 * k + 2], hb.x); fma2(a1, w[4 * k + 3], hb.y);     \
        }                                                                   \
    } else if (wid == 10) {                                                 \
        const ulonglong2* hp = (const ulonglong2*)(&h1ring[(RSLOT)][24]);   \
        _Pragma("unroll")                                                   \
        for (int k = 0; k < 3; k++) {                                       \
            ulonglong2 ha = hp[2 * k]; ulonglong2 hb = hp[2 * k + 1];       \
            fma2(a0, w[4 * k + 0], ha.x); fma2(a1, w[4 * k + 1], ha.y);     \
            fma2(a0, w[4 * k + 2], hb.x); fma2(a1, w[4 * k + 3], hb.y);     \
        }                                                                   \
    } else {                                                                \
        const ulonglong2* hp = (const ulonglong2*)(&h1ring[(RSLOT)][48]);   \
        _Pragma("unroll")                                                   \
        for (int k = 0; k < 2; k++) {                                       \
            ulonglong2 ha = hp[2 * k]; ulonglong2 hb = hp[2 * k + 1];       \
            fma2(a0, w[4 * k + 0], ha.x); fma2(a1, w[4 * k + 1], ha.y);     \
            fma2(a0, w[4 * k + 2], hb.x); fma2(a1, w[4 * k + 3], hb.y);     \
        }                                                                   \
    }                                                                       \
    add2(a0, a1);                                                           \
    float2 s2h = upk2(a0);                                                  \
    pbuf[(WPH)][wid - 9][lane] = s2h.x + s2h.y;                             \
} while (0)

#define PROJ_STEP(T) do {                                                   \
    const int s2i = (T) - 34 + lane;                                        \
    if (s2i >= 0) {                                                         \
        const float* r = &h2ring[(s2i & (RING - 1)) * RSTR];                \
        float acc0 = boutv, acc1 = 0.f;                                     \
        _Pragma("unroll")                                                   \
        for (int k = 0; k < 4; k++) {                                       \
            acc0 = fmaf(r[2 * k],     w2h[2 * k],     acc0);                \
            acc1 = fmaf(r[2 * k + 1], w2h[2 * k + 1], acc1);                \
        }                                                                   \
        yb[s2i] = acc0 + acc1 + xb[s2i];                                    \
    }                                                                       \
} while (0)

// fully guarded generic step (prologue/epilogue only)
#define GT_STEP(T) do {                                                     \
    if (wid < 8) {                                                          \
        if ((T) < Tn) { float xc = xb[(T)];                                 \
            L1_STEP((T), xc, ((T) + 3) & 3, (T) & 3); }                     \
    } else if (wid == 8) {                                                  \
        if ((T) >= 2) W8_STEP((T), ((T) - 1) & 1, (T) & 1);                 \
    } else {                                                                \
        if ((T) >= 1 && (T) <= Tn) HELPER_STEP((T), ((T) - 1) & 3, (T) & 1);\
        if (wid == 11 && ((T) & 31) == 0 && (T) >= 32) PROJ_STEP(T);        \
    }                                                                       \
    __syncthreads();                                                        \
} while (0)

// unguarded fast step, t = tc + K with tc % 4 == 0 (slots/phases baked)
#define FAST_STEP(T, XC, K) do {                                            \
    if (wid < 8) {                                                          \
        L1_STEP((T), (XC), ((K) + 3) & 3, (K) & 3);                         \
    } else if (wid == 8) {                                                  \
        W8_STEP((T), ((K) + 1) & 1, (K) & 1);                               \
    } else {                                                                \
        HELPER_STEP((T), ((K) + 3) & 3, (K) & 1);                           \
        if ((K) == 0 && wid == 11 && ((T) & 31) == 0) PROJ_STEP(T);         \
    }                                                                       \
    __syncthreads();                                                        \
} while (0)

__global__ void __launch_bounds__(384, 1) lstm2_kernel(
    const float* __restrict__ x,
    const float* __restrict__ Wih1,
    const float* __restrict__ Whh1,
    const float* __restrict__ b1,
    const float* __restrict__ Wih2,
    const float* __restrict__ Whh2,
    const float* __restrict__ b2,
    const float* __restrict__ Wout,
    const float* __restrict__ bout,
    float* __restrict__ out)
{
    const int b    = blockIdx.x;
    const int tid  = threadIdx.x;
    const int wid  = tid >> 5;
    const int lane = tid & 31;
    const unsigned bl = lane & ~3u;

    __shared__ __align__(16) float h1ring[4][H1n];
    __shared__ __align__(16) float pbuf[2][3][32];   // [phase][src][cell*4+gate]
    __shared__ __align__(16) float h2s[2][H2n];      // h2 double buffer
    __shared__ float h2ring[RING * RSTR];

    const float* xb = x + (size_t)b * Tn;
    float*       yb = out + (size_t)b * Tn;

    u64   w[32];                       // L1: 32; warp8: 16; helpers: <=12
    float wih = 0.f, bias = 0.f;
    float c1 = 0.f, h1v = 0.f;
    float w2h[8];
    float bias2 = 0.f, boutv = 0.f;
    float c2 = 0.f, h2v = 0.f;
    int   cell = 0, q = 0;

    if (wid < 8) {
        cell = wid * 8 + (lane >> 2);
        q    = lane & 3;
        const int row = q * H1n + cell;
        const float2* wp = (const float2*)(Whh1 + row * H1n);
        #pragma unroll
        for (int k = 0; k < 32; k++) { float2 f = wp[k]; w[k] = pk2(f.x, f.y); }
        wih  = Wih1[row];
        bias = b1[row];
        if (tid < H1n) h1ring[3][tid] = 0.0f;   // h1[-1] = 0
    } else if (wid == 8) {
        if (lane < H2n) {
            #pragma unroll
            for (int g = 0; g < 4; g++) {
                const int row = g * H2n + lane;
                const float2* wp = (const float2*)(Whh2 + row * H2n);
                #pragma unroll
                for (int j = 0; j < 4; j++) { float2 f = wp[j]; w[4 * g + j] = pk2(f.x, f.y); }
            }
            h2s[0][lane] = 0.0f;
            h2s[1][lane] = 0.0f;
        }
    } else { // wid 9..11 : K-split input-dot helpers
        cell = lane >> 2;
        q    = lane & 3;
        const int row = q * H2n + cell;
        const int koff = (wid == 9) ? 0 : (wid == 10) ? 24 : 48;
        const int kcnt = (wid == 11) ? 16 : 24;       // floats
        const float2* wp = (const float2*)(Wih2 + row * H1n + koff);
        for (int k = 0; k < kcnt / 2; k++) { float2 f = wp[k]; w[k] = pk2(f.x, f.y); }
        bias2 = (wid == 9) ? b2[row] : 0.f;
        if (wid == 11) {
            #pragma unroll
            for (int k = 0; k < 8; k++) w2h[k] = Wout[k];
            boutv = bout[0];
        }
    }
    __syncthreads();

    // prologue: t = 0..3 (guarded)
    GT_STEP(0); GT_STEP(1); GT_STEP(2); GT_STEP(3);

    // main loop: t = 4 .. Tn-9, chunks of 4 with baked slots/phases.
    float4 cur4 = make_float4(0.f, 0.f, 0.f, 0.f);
    if (wid < 8) cur4 = *(const float4*)(xb + 4);
    for (int tc = 4; tc < Tn - 8; tc += 4) {
        float4 nxt4 = cur4;
        if (wid < 8) nxt4 = *(const float4*)(xb + tc + 4);
        FAST_STEP(tc + 0, cur4.x, 0);
        FAST_STEP(tc + 1, cur4.y, 1);
        FAST_STEP(tc + 2, cur4.z, 2);
        FAST_STEP(tc + 3, cur4.w, 3);
        cur4 = nxt4;
    }

    // epilogue: t = Tn-8 .. Tn+1 (guarded)
    for (int t = Tn - 8; t <= Tn + 1; ++t) GT_STEP(t);

    // tail: y for the last two steps (s = Tn-2, Tn-1) from the ring
    if (wid == 11 && lane < 2) {
        const int s2i = Tn - 2 + lane;
        const float* r = &h2ring[(s2i & (RING - 1)) * RSTR];
        float acc0 = boutv, acc1 = 0.f;
        #pragma unroll
        for (int k = 0; k < 4; k++) {
            acc0 = fmaf(r[2 * k],     w2h[2 * k],     acc0);
            acc1 = fmaf(r[2 * k + 1], w2h[2 * k + 1], acc1);
        }
        yb[s2i] = acc0 + acc1 + xb[s2i];
    }

    // final states: layout  y | h1 | c1 | h2 | c2  (each with leading dim 1)
    const int OH1 = Bsz * Tn;
    const int OC1 = OH1 + Bsz * H1n;
    const int OH2 = OC1 + Bsz * H1n;
    const int OC2 = OH2 + Bsz * H2n;
    if (wid < 8) {
        if (q == 0) {
            out[OH1 + b * H1n + cell] = h1v;
            out[OC1 + b * H1n + cell] = c1;
        }
    } else if (wid == 8) {
        if (lane < H2n) {
            out[OH2 + b * H2n + lane] = h2v;
            out[OC2 + b * H2n + lane] = c2;
        }
    }
}

extern "C" void kernel_launch(void* const* d_in, const int* in_sizes, int n_in,
                              void* d_out, int out_size) {
    const float* x     = (const float*)d_in[0];
    const float* Wih1  = (const float*)d_in[1];
    const float* Whh1  = (const float*)d_in[2];
    const float* b1    = (const float*)d_in[3];
    const float* Wih2  = (const float*)d_in[4];
    const float* Whh2  = (const float*)d_in[5];
    const float* b2    = (const float*)d_in[6];
    const float* Wout  = (const float*)d_in[7];
    const float* bout  = (const float*)d_in[8];
    float* out = (float*)d_out;

    lstm2_kernel<<<Bsz, 384>>>(x, Wih1, Whh1, b1, Wih2, Whh2, b2, Wout, bout, out);
}

// round 12
// speedup vs baseline: 1.6638x; 1.1144x over previous
#include <cuda_runtime.h>

#define Bsz 64
#define Tn  16384
#define H1n 64
#define H2n 8
#define RING 64
#define RSTR 8   // 32B rows: 16B-aligned for warp-8 LDS.128 re-reads

typedef unsigned long long u64;

__device__ __forceinline__ u64 pk2(float lo, float hi) {
    u64 r; asm("mov.b64 %0, {%1,%2};" : "=l"(r) : "f"(lo), "f"(hi)); return r;
}
__device__ __forceinline__ float2 upk2(u64 v) {
    float2 f; asm("mov.b64 {%0,%1}, %2;" : "=f"(f.x), "=f"(f.y) : "l"(v)); return f;
}
__device__ __forceinline__ void fma2(u64 &d, u64 a, u64 b) {
    asm("fma.rn.f32x2 %0, %1, %2, %0;" : "+l"(d) : "l"(a), "l"(b));
}
__device__ __forceinline__ void add2(u64 &d, u64 a) {
    asm("add.rn.f32x2 %0, %0, %1;" : "+l"(d) : "l"(a));
}
__device__ __forceinline__ float tanh_(float v) {
    float r; asm("tanh.approx.f32 %0, %1;" : "=f"(r) : "f"(v)); return r;
}
__device__ __forceinline__ float sigm(float v) {
    return fmaf(0.5f, tanh_(0.5f * v), 0.5f);
}

// One block per batch row. 11 warps (352 threads):
//   warps 0-7 : layer-1, lane = cellLocal*4 + gate, 8 cells/warp, 64-dot.
//   warp 8    : layer-2 update (lags 2), one lane per cell (lanes 0-7):
//               gates in-lane; pbuf partials via 2x float4 LDS; h2(t-1)
//               re-read from the h2 ring (32B rows, aligned LDS.128).
//               ALSO does the batched output projection (all 32 lanes,
//               once per 32 steps — amortized off the critical chain).
//   warps 9-10: layer-2 input dot Wih2@h1[t-1], K-split 32/32, one step
//               ahead of warp 8, partials into double-buffered pbuf.
// h1 in a depth-4 smem ring; one __syncthreads per step orders hand-offs.
// vs R7: fewer barrier participants (12->11) and fewer STS in flight
// (13->11) to cut the BAR drain cost.
__global__ void __launch_bounds__(352, 1) lstm2_kernel(
    const float* __restrict__ x,
    const float* __restrict__ Wih1,
    const float* __restrict__ Whh1,
    const float* __restrict__ b1,
    const float* __restrict__ Wih2,
    const float* __restrict__ Whh2,
    const float* __restrict__ b2,
    const float* __restrict__ Wout,
    const float* __restrict__ bout,
    float* __restrict__ out)
{
    const int b    = blockIdx.x;
    const int tid  = threadIdx.x;
    const int wid  = tid >> 5;
    const int lane = tid & 31;

    __shared__ __align__(16) float h1ring[4][H1n];
    __shared__ __align__(16) float pbuf[2][2][32];   // [phase][src][cell*4+gate]
    __shared__ __align__(16) float h2ring[RING * RSTR];

    const float* xb = x + (size_t)b * Tn;
    float*       yb = out + (size_t)b * Tn;

    u64   w[32];                       // L1: 32; warp8: 16; helpers: 16
    float wih = 0.f, bias = 0.f;
    float c1 = 0.f, h1v = 0.f;
    float w2h[8];                      // warp8: Wout taps for projection
    float bias2 = 0.f, boutv = 0.f;
    float c2 = 0.f, h2v = 0.f;
    int   cell = 0, q = 0;

    if (wid < 8) {
        cell = wid * 8 + (lane >> 2);
        q    = lane & 3;
        const int row = q * H1n + cell;
        const float2* wp = (const float2*)(Whh1 + row * H1n);
        #pragma unroll
        for (int k = 0; k < 32; k++) { float2 f = wp[k]; w[k] = pk2(f.x, f.y); }
        wih  = Wih1[row];
        bias = b1[row];
        if (tid < H1n) h1ring[3][tid] = 0.0f;   // h1[-1] = 0
    } else if (wid == 8) {
        // lanes 0-7: lane = cell, all 4 gates in-lane
        if (lane < H2n) {
            #pragma unroll
            for (int g = 0; g < 4; g++) {
                const int row = g * H2n + lane;
                const float2* wp = (const float2*)(Whh2 + row * H2n);
                #pragma unroll
                for (int j = 0; j < 4; j++) { float2 f = wp[j]; w[4 * g + j] = pk2(f.x, f.y); }
            }
            h2ring[63 * RSTR + lane] = 0.0f;    // h2[-1] = 0 (read at t=2)
        }
        #pragma unroll
        for (int k = 0; k < 8; k++) w2h[k] = Wout[k];
        boutv = bout[0];
    } else { // wid 9,10 : K-split input-dot helpers (32/32)
        cell = lane >> 2;
        q    = lane & 3;
        const int row = q * H2n + cell;
        const int koff = (wid == 9) ? 0 : 32;
        const float2* wp = (const float2*)(Wih2 + row * H1n + koff);
        #pragma unroll
        for (int k = 0; k < 16; k++) { float2 f = wp[k]; w[k] = pk2(f.x, f.y); }
        bias2 = (wid == 9) ? b2[row] : 0.f;
    }
    __syncthreads();

    float x_cur = xb[0];
    float x_n1  = xb[1];

    #pragma unroll 4
    for (int t = 0; t <= Tn + 1; ++t) {
        if (wid < 8) {
            if (t < Tn) {
                float x_n2 = (t + 2 < Tn) ? xb[t + 2] : 0.0f;
                u64 a0 = pk2(fmaf(x_cur, wih, bias), 0.0f);
                u64 a1 = pk2(0.f, 0.f), a2 = a1, a3 = a1;
                const ulonglong2* hp = (const ulonglong2*)(&h1ring[(t + 3) & 3][0]);
                #pragma unroll
                for (int k = 0; k < 8; k++) {
                    ulonglong2 ha = hp[2 * k];
                    ulonglong2 hb = hp[2 * k + 1];
                    fma2(a0, w[4 * k + 0], ha.x);
                    fma2(a1, w[4 * k + 1], ha.y);
                    fma2(a2, w[4 * k + 2], hb.x);
                    fma2(a3, w[4 * k + 3], hb.y);
                }
                add2(a0, a1); add2(a2, a3); add2(a0, a2);
                float2 s2 = upk2(a0);
                float g = s2.x + s2.y;
                float act = (q == 2) ? tanh_(g) : sigm(g);
                const unsigned bl = lane & ~3u;
                float ai = __shfl_sync(0xffffffffu, act, bl + 0);
                float af = __shfl_sync(0xffffffffu, act, bl + 1);
                float ag = __shfl_sync(0xffffffffu, act, bl + 2);
                float ao = __shfl_sync(0xffffffffu, act, bl + 3);
                c1  = fmaf(af, c1, ai * ag);
                h1v = ao * tanh_(c1);
                if (q == 0) h1ring[t & 3][cell] = h1v;
                x_cur = x_n1;
                x_n1  = x_n2;
            }
        } else if (wid == 8) {
            if (t >= 2) {
                if (lane < H2n) {
                    const int s  = t - 2;
                    const int ph = (t - 1) & 1;
                    const float4 p0 = *(const float4*)&pbuf[ph][0][lane * 4];
                    const float4 p1 = *(const float4*)&pbuf[ph][1][lane * 4];
                    float gi = p0.x + p1.x;
                    float gf = p0.y + p1.y;
                    float gg = p0.z + p1.z;
                    float go = p0.w + p1.w;
                    // h2(t-1) from the ring (written by this warp at t-1)
                    const u64* hq = (const u64*)&h2ring[((t - 3) & (RING - 1)) * RSTR];
                    u64 h01 = hq[0], h23 = hq[1], h45 = hq[2], h67 = hq[3];
                    u64 A = pk2(gi, 0.f), B = pk2(gf, 0.f);
                    u64 C = pk2(gg, 0.f), D = pk2(go, 0.f);
                    fma2(A, w[0],  h01); fma2(B, w[4],  h01);
                    fma2(C, w[8],  h01); fma2(D, w[12], h01);
                    fma2(A, w[1],  h23); fma2(B, w[5],  h23);
                    fma2(C, w[9],  h23); fma2(D, w[13], h23);
                    fma2(A, w[2],  h45); fma2(B, w[6],  h45);
                    fma2(C, w[10], h45); fma2(D, w[14], h45);
                    fma2(A, w[3],  h67); fma2(B, w[7],  h67);
                    fma2(C, w[11], h67); fma2(D, w[15], h67);
                    float2 fa = upk2(A), fb = upk2(B), fc = upk2(C), fd = upk2(D);
                    float ti = sigm(fa.x + fa.y);
                    float tf = sigm(fb.x + fb.y);
                    float tg = tanh_(fc.x + fc.y);
                    float to = sigm(fd.x + fd.y);
                    c2  = fmaf(tf, c2, ti * tg);
                    h2v = to * tanh_(c2);
                    h2ring[(s & (RING - 1)) * RSTR + lane] = h2v;
                }
                // batched output projection (all 32 lanes, every 32 steps);
                // ring rows for [t-34, t-3] are all written (warp-internal
                // ordering makes this warp's own STS visible).
                if ((t & 31) == 0 && t >= 32) {
                    const int s2i = t - 34 + lane;
                    if (s2i >= 0) {
                        const float* r = &h2ring[(s2i & (RING - 1)) * RSTR];
                        float acc0 = boutv, acc1 = 0.f;
                        #pragma unroll
                        for (int k = 0; k < 4; k++) {
                            acc0 = fmaf(r[2 * k],     w2h[2 * k],     acc0);
                            acc1 = fmaf(r[2 * k + 1], w2h[2 * k + 1], acc1);
                        }
                        yb[s2i] = acc0 + acc1 + xb[s2i];
                    }
                }
            }
        } else { // wid 9,10 : layer-2 input-dot partials (for step s = t-1)
            if (t >= 1 && t <= Tn) {
                const int s = t - 1;
                u64 a0 = pk2(bias2, 0.0f), a1 = pk2(0.f, 0.f);
                const int koff = (wid == 9) ? 0 : 32;
                const ulonglong2* hp = (const ulonglong2*)(&h1ring[s & 3][koff]);
                #pragma unroll
                for (int k = 0; k < 4; k++) {
                    ulonglong2 ha = hp[2 * k];
                    ulonglong2 hb = hp[2 * k + 1];
                    fma2(a0, w[4 * k + 0], ha.x);
                    fma2(a1, w[4 * k + 1], ha.y);
                    fma2(a0, w[4 * k + 2], hb.x);
                    fma2(a1, w[4 * k + 3], hb.y);
                }
                add2(a0, a1);
                float2 s2 = upk2(a0);
                pbuf[t & 1][wid - 9][lane] = s2.x + s2.y;
            }
        }
        __syncthreads();
    }

    // tail: y for the last two steps (s = Tn-2, Tn-1) from the ring
    if (wid == 8 && lane < 2) {
        const int s2i = Tn - 2 + lane;
        const float* r = &h2ring[(s2i & (RING - 1)) * RSTR];
        float acc0 = boutv, acc1 = 0.f;
        #pragma unroll
        for (int k = 0; k < 4; k++) {
            acc0 = fmaf(r[2 * k],     w2h[2 * k],     acc0);
            acc1 = fmaf(r[2 * k + 1], w2h[2 * k + 1], acc1);
        }
        yb[s2i] = acc0 + acc1 + xb[s2i];
    }

    // final states: layout  y | h1 | c1 | h2 | c2  (each with leading dim 1)
    const int OH1 = Bsz * Tn;
    const int OC1 = OH1 + Bsz * H1n;
    const int OH2 = OC1 + Bsz * H1n;
    const int OC2 = OH2 + Bsz * H2n;
    if (wid < 8) {
        if (q == 0) {
            out[OH1 + b * H1n + cell] = h1v;
            out[OC1 + b * H1n + cell] = c1;
        }
    } else if (wid == 8) {
        if (lane < H2n) {
            out[OH2 + b * H2n + lane] = h2v;
            out[OC2 + b * H2n + lane] = c2;
        }
    }
}

extern "C" void kernel_launch(void* const* d_in, const int* in_sizes, int n_in,
                              void* d_out, int out_size) {
    const float* x     = (const float*)d_in[0];
    const float* Wih1  = (const float*)d_in[1];
    const float* Whh1  = (const float*)d_in[2];
    const float* b1    = (const float*)d_in[3];
    const float* Wih2  = (const float*)d_in[4];
    const float* Whh2  = (const float*)d_in[5];
    const float* b2    = (const float*)d_in[6];
    const float* Wout  = (const float*)d_in[7];
    const float* bout  = (const float*)d_in[8];
    float* out = (float*)d_out;

    lstm2_kernel<<<Bsz, 352>>>(x, Wih1, Whh1, b1, Wih2, Whh2, b2, Wout, bout, out);
}